// round 11
// baseline (speedup 1.0000x reference)
#include <cuda_runtime.h>
#include <cuda_fp16.h>
#include <cstdint>

#define B_ 2
#define S_ 4096
#define H_ 3584
#define NH_ 28
#define NKV_ 4
#define D_ 128

constexpr int M_   = B_ * S_;                 // 8192
constexpr int K_   = H_;                      // 3584
constexpr int NTOT = (NH_ + 2 * NKV_) * D_;   // 4608
constexpr long QSIZE = (long)B_ * NH_ * S_ * D_;
constexpr long KSIZE = (long)B_ * NKV_ * S_ * D_;

constexpr int BM = 128, BN = 128;
constexpr int NC = K_ / 32;                   // 112 chunks of 32 K
constexpr int NSTAGE = 4;
constexpr int STAGE_BYTES = 16384;            // A 8KB (128x64B) + B 8KB (128x64B)
constexpr int A_BYTES = 8192;
constexpr int SROW = 132;
constexpr int SMEM_TOTAL = (NSTAGE * STAGE_BYTES > BM * SROW * 4)
                         ? NSTAGE * STAGE_BYTES : BM * SROW * 4;  // 67584

// ---------------- scratch ----------------
__device__ __half g_Apack[(long)M_ * K_];     // [m][k] fp16
__device__ __half g_Bpack[(long)NTOT * K_];   // [n][k] fp16

// ---------------- helpers ----------------
__device__ __forceinline__ uint32_t smem_u32(const void* p) {
    uint32_t a;
    asm("{ .reg .u64 t; cvta.to.shared.u64 t, %1; cvt.u32.u64 %0, t; }" : "=r"(a) : "l"(p));
    return a;
}
__device__ __forceinline__ uint32_t swz64(uint32_t off)  { return off ^ ((off >> 3) & 0x30); }

__device__ __forceinline__ void cp16(uint32_t dst, const void* src) {
    asm volatile("cp.async.cg.shared.global [%0], [%1], 16;" :: "r"(dst), "l"(src));
}
#define CP_COMMIT() asm volatile("cp.async.commit_group;" ::: "memory")
#define CP_WAIT2()  asm volatile("cp.async.wait_group 2;" ::: "memory")
#define CP_WAIT0()  asm volatile("cp.async.wait_group 0;" ::: "memory")

__device__ __forceinline__ void ldm_x4(uint32_t* r, uint32_t addr) {
    asm volatile("ldmatrix.sync.aligned.m8n8.x4.shared.b16 {%0,%1,%2,%3}, [%4];"
                 : "=r"(r[0]), "=r"(r[1]), "=r"(r[2]), "=r"(r[3]) : "r"(addr));
}
__device__ __forceinline__ void mma_f16(float* c, const uint32_t* a, const uint32_t* b) {
    asm volatile("mma.sync.aligned.m16n8k16.row.col.f32.f16.f16.f32 "
                 "{%0,%1,%2,%3},{%4,%5,%6,%7},{%8,%9},{%0,%1,%2,%3};"
                 : "+f"(c[0]), "+f"(c[1]), "+f"(c[2]), "+f"(c[3])
                 : "r"(a[0]), "r"(a[1]), "r"(a[2]), "r"(a[3]), "r"(b[0]), "r"(b[1]));
}

// ---------------- merged conversion kernel ----------------
constexpr int NA_BLOCKS = (M_ * K_ / 4) / 256;            // 28672
constexpr int NBK = K_ / 32;                               // 112
constexpr int NB_BLOCKS = NBK * (NTOT / 32);               // 16128

__global__ void conv_kernel(const float* __restrict__ hid,
                            const float* __restrict__ Wq,
                            const float* __restrict__ Wk,
                            const float* __restrict__ Wv) {
    int bid = blockIdx.x;
    if (bid < NA_BLOCKS) {
        long i4 = (long)bid * 256 + threadIdx.x;
        float4 v = reinterpret_cast<const float4*>(hid)[i4];
        __half h[4] = {__float2half_rn(v.x), __float2half_rn(v.y),
                       __float2half_rn(v.z), __float2half_rn(v.w)};
        *reinterpret_cast<ushort4*>(&g_Apack[i4 * 4]) = *reinterpret_cast<ushort4*>(h);
        return;
    }
    __shared__ float tile[32][33];
    int b2 = bid - NA_BLOCKS;
    int k0 = (b2 % NBK) * 32;
    int n0 = (b2 / NBK) * 32;
    const float* W; int ldw, nc;
    if (n0 < NH_ * D_)               { W = Wq; ldw = NH_ * D_;  nc = n0; }
    else if (n0 < (NH_ + NKV_) * D_) { W = Wk; ldw = NKV_ * D_; nc = n0 - NH_ * D_; }
    else                             { W = Wv; ldw = NKV_ * D_; nc = n0 - (NH_ + NKV_) * D_; }
    int tx = threadIdx.x & 31, ty = threadIdx.x >> 5;
#pragma unroll
    for (int r = 0; r < 4; r++)
        tile[ty + r * 8][tx] = W[(long)(k0 + ty + r * 8) * ldw + nc + tx];
    __syncthreads();
#pragma unroll
    for (int r = 0; r < 4; r++) {
        int nl = ty + r * 8;
        g_Bpack[(long)(n0 + nl) * K_ + k0 + tx] = __float2half_rn(tile[tx][nl]);
    }
}

// ---------------- fused GEMM + bias + RoPE (256 thr, 2 CTA/SM, 64x32 warp tiles) ----------------
__global__ __launch_bounds__(256, 2)
void qkv_mma_kernel(const float* __restrict__ cosp, const float* __restrict__ sinp,
                    const float* __restrict__ bq, const float* __restrict__ bk,
                    const float* __restrict__ bv, float* __restrict__ out) {
    extern __shared__ char smem[];
    const uint32_t sbase = smem_u32(smem);
    const int tid  = threadIdx.x;
    const int wid  = tid >> 5, lane = tid & 31;
    const int m0   = blockIdx.y * BM;
    const int hg   = blockIdx.x;              // one head per CTA
    const int n0   = hg * BN;

    const int warp_m = wid & 1;               // 2 warps over M (64 rows each)
    const int warp_n = wid >> 1;              // 4 warps over N (32 cols each)

    const __half* Agb = g_Apack + (long)m0 * K_;
    const __half* Bgb = g_Bpack + (long)n0 * K_;

    // stage loader: A 512x16B + B 512x16B (both SW64), 256 threads -> 2+2 each
    auto load_stage = [&](int c, int s) {
        const uint32_t ab = sbase + (uint32_t)(s * STAGE_BYTES);
        const uint32_t bb = ab + A_BYTES;
        const __half* Ag = Agb + (long)c * 32;
        const __half* Bg = Bgb + (long)c * 32;
#pragma unroll
        for (int i = 0; i < 2; i++) {
            int e = tid + i * 256, row = e >> 2, q = e & 3;   // 128 rows x 4 units
            cp16(ab + swz64(row * 64 + q * 16), Ag + (long)row * K_ + q * 8);
        }
#pragma unroll
        for (int i = 0; i < 2; i++) {
            int e = tid + i * 256, row = e >> 2, q = e & 3;
            cp16(bb + swz64(row * 64 + q * 16), Bg + (long)row * K_ + q * 8);
        }
    };

    float acc[4][4][4];
#pragma unroll
    for (int i = 0; i < 4; i++)
#pragma unroll
        for (int j = 0; j < 4; j++)
#pragma unroll
            for (int r = 0; r < 4; r++) acc[i][j][r] = 0.f;

    load_stage(0, 0); CP_COMMIT();
    load_stage(1, 1); CP_COMMIT();
    load_stage(2, 2); CP_COMMIT();

    const int a_row = lane & 15;
    const int a_cb  = (lane >> 4) * 16;
    const int b_row = ((lane >> 4) << 3) + (lane & 7);
    const int b_cb  = ((lane >> 3) & 1) * 16;

    for (int c = 0; c < NC; c++) {
        CP_WAIT2();
        __syncthreads();                      // stage c ready; all warps done with c-1

        if (c + 3 < NC) load_stage(c + 3, (c + 3) & 3);
        CP_COMMIT();

        const uint32_t ab = sbase + (uint32_t)((c & 3) * STAGE_BYTES);
        const uint32_t bb = ab + A_BYTES;

#pragma unroll
        for (int ks = 0; ks < 2; ks++) {
            uint32_t af[4][4], bf[2][4];
#pragma unroll
            for (int mt = 0; mt < 4; mt++) {
                uint32_t off = (uint32_t)(warp_m * 64 + mt * 16 + a_row) * 64 + ks * 32 + a_cb;
                ldm_x4(af[mt], ab + swz64(off));
            }
#pragma unroll
            for (int bt = 0; bt < 2; bt++) {
                uint32_t off = (uint32_t)(warp_n * 32 + bt * 16 + b_row) * 64 + ks * 32 + b_cb;
                ldm_x4(bf[bt], bb + swz64(off));
            }
#pragma unroll
            for (int mt = 0; mt < 4; mt++)
#pragma unroll
                for (int nt = 0; nt < 4; nt++)
                    mma_f16(acc[mt][nt], af[mt], &bf[nt >> 1][(nt & 1) * 2]);
        }
    }

    CP_WAIT0();
    __syncthreads();

    // ---- epilogue: accums -> smem stage ----
    float* stage = reinterpret_cast<float*>(smem);
#pragma unroll
    for (int mt = 0; mt < 4; mt++) {
#pragma unroll
        for (int nt = 0; nt < 4; nt++) {
            int row = warp_m * 64 + mt * 16 + (lane >> 2);
            int col = warp_n * 32 + nt * 8 + (lane & 3) * 2;
            *reinterpret_cast<float2*>(&stage[row * SROW + col]) =
                make_float2(acc[mt][nt][0], acc[mt][nt][1]);
            *reinterpret_cast<float2*>(&stage[(row + 8) * SROW + col]) =
                make_float2(acc[mt][nt][2], acc[mt][nt][3]);
        }
    }
    __syncthreads();

    // ---- bias + RoPE + coalesced store (one head) ----
    bool rope; const float* bias; float* ob; int nheads, hloc;
    if (hg < NH_)             { rope = true;  bias = bq; ob = out;                 nheads = NH_;  hloc = hg; }
    else if (hg < NH_ + NKV_) { rope = true;  bias = bk; ob = out + QSIZE;         nheads = NKV_; hloc = hg - NH_; }
    else                      { rope = false; bias = bv; ob = out + QSIZE + KSIZE; nheads = NKV_; hloc = hg - NH_ - NKV_; }

    const int j0 = lane * 4;                 // own columns
    const int p0 = (j0 + 64) & 127;          // partner columns
    const int d  = j0 & 63;
    float4 bo = *reinterpret_cast<const float4*>(bias + hloc * D_ + j0);
    float4 bp = *reinterpret_cast<const float4*>(bias + hloc * D_ + p0);

    for (int r = 0; r < 16; r++) {
        int row = wid * 16 + r;              // 8 warps x 16 rows = 128
        int m2 = m0 + row;
        int bi = m2 >> 12, sq = m2 & (S_ - 1);
        float4 own = *reinterpret_cast<const float4*>(&stage[row * SROW + j0]);
        float4 par = *reinterpret_cast<const float4*>(&stage[row * SROW + p0]);
        own.x += bo.x; own.y += bo.y; own.z += bo.z; own.w += bo.w;
        par.x += bp.x; par.y += bp.y; par.z += bp.z; par.w += bp.w;
        float4 o;
        if (rope) {
            float4 cc = *reinterpret_cast<const float4*>(cosp + (long)m2 * D_ + d);
            float4 ss = *reinterpret_cast<const float4*>(sinp + (long)m2 * D_ + d);
            if (lane < 16) {   // own = lo half: o = lo*c - hi*s
                o.x = own.x * cc.x - par.x * ss.x;
                o.y = own.y * cc.y - par.y * ss.y;
                o.z = own.z * cc.z - par.z * ss.z;
                o.w = own.w * cc.w - par.w * ss.w;
            } else {           // own = hi half: o = hi*c + lo*s
                o.x = own.x * cc.x + par.x * ss.x;
                o.y = own.y * cc.y + par.y * ss.y;
                o.z = own.z * cc.z + par.z * ss.z;
                o.w = own.w * cc.w + par.w * ss.w;
            }
        } else {
            o = own;
        }
        float* optr = ob + ((long)(bi * nheads + hloc) * S_ + sq) * D_;
        *reinterpret_cast<float4*>(optr + j0) = o;
    }
}

// ---------------- launch ----------------
extern "C" void kernel_launch(void* const* d_in, const int* in_sizes, int n_in,
                              void* d_out, int out_size) {
    (void)in_sizes; (void)n_in; (void)out_size;
    const float* hid  = (const float*)d_in[0];
    const float* cosp = (const float*)d_in[1];
    const float* sinp = (const float*)d_in[2];
    const float* Wq   = (const float*)d_in[3];
    const float* bq   = (const float*)d_in[4];
    const float* Wk   = (const float*)d_in[5];
    const float* bk   = (const float*)d_in[6];
    const float* Wv   = (const float*)d_in[7];
    const float* bv   = (const float*)d_in[8];
    float* out = (float*)d_out;

    cudaFuncSetAttribute(qkv_mma_kernel, cudaFuncAttributeMaxDynamicSharedMemorySize, SMEM_TOTAL);

    conv_kernel<<<NA_BLOCKS + NB_BLOCKS, 256>>>(hid, Wq, Wk, Wv);
    qkv_mma_kernel<<<dim3(NTOT / BN, M_ / BM), 256, SMEM_TOTAL>>>(cosp, sinp, bq, bk, bv, out);
}

// round 12
// speedup vs baseline: 1.2165x; 1.2165x over previous
#include <cuda_runtime.h>
#include <cuda_fp16.h>
#include <cstdint>

#define B_ 2
#define S_ 4096
#define H_ 3584
#define NH_ 28
#define NKV_ 4
#define D_ 128

constexpr int M_   = B_ * S_;                 // 8192
constexpr int K_   = H_;                      // 3584
constexpr int NTOT = (NH_ + 2 * NKV_) * D_;   // 4608
constexpr long QSIZE = (long)B_ * NH_ * S_ * D_;
constexpr long KSIZE = (long)B_ * NKV_ * S_ * D_;

constexpr int BM = 128, BN = 128;
constexpr int NC = K_ / 32;                   // 112 chunks of 32 K
constexpr int NSTAGE = 4;
constexpr int STAGE_BYTES = 16384;            // A 8KB (128x64B) + B 8KB (128x64B)
constexpr int A_BYTES = 8192;
constexpr int SROW = 132;
constexpr int SMEM_TOTAL = (NSTAGE * STAGE_BYTES > BM * SROW * 4)
                         ? NSTAGE * STAGE_BYTES : BM * SROW * 4;  // 67584

// ---------------- scratch ----------------
__device__ __half g_Apack[(long)M_ * K_];     // [m][k] fp16
__device__ __half g_Bpack[(long)NTOT * K_];   // [n][k] fp16

// ---------------- helpers ----------------
__device__ __forceinline__ uint32_t smem_u32(const void* p) {
    uint32_t a;
    asm("{ .reg .u64 t; cvta.to.shared.u64 t, %1; cvt.u32.u64 %0, t; }" : "=r"(a) : "l"(p));
    return a;
}
__device__ __forceinline__ uint32_t swz64(uint32_t off)  { return off ^ ((off >> 3) & 0x30); }

__device__ __forceinline__ void cp16(uint32_t dst, const void* src) {
    asm volatile("cp.async.cg.shared.global [%0], [%1], 16;" :: "r"(dst), "l"(src));
}
#define CP_COMMIT() asm volatile("cp.async.commit_group;" ::: "memory")
#define CP_WAIT2()  asm volatile("cp.async.wait_group 2;" ::: "memory")
#define CP_WAIT0()  asm volatile("cp.async.wait_group 0;" ::: "memory")

__device__ __forceinline__ void ldm_x4(uint32_t* r, uint32_t addr) {
    asm volatile("ldmatrix.sync.aligned.m8n8.x4.shared.b16 {%0,%1,%2,%3}, [%4];"
                 : "=r"(r[0]), "=r"(r[1]), "=r"(r[2]), "=r"(r[3]) : "r"(addr));
}
__device__ __forceinline__ void mma_f16(float* c, const uint32_t* a, const uint32_t* b) {
    asm volatile("mma.sync.aligned.m16n8k16.row.col.f32.f16.f16.f32 "
                 "{%0,%1,%2,%3},{%4,%5,%6,%7},{%8,%9},{%0,%1,%2,%3};"
                 : "+f"(c[0]), "+f"(c[1]), "+f"(c[2]), "+f"(c[3])
                 : "r"(a[0]), "r"(a[1]), "r"(a[2]), "r"(a[3]), "r"(b[0]), "r"(b[1]));
}

// ---------------- merged conversion kernel ----------------
constexpr int NA_BLOCKS = (M_ * K_ / 4) / 256;            // 28672
constexpr int NBK = K_ / 32;                               // 112
constexpr int NB_BLOCKS = NBK * (NTOT / 32);               // 16128

__global__ void conv_kernel(const float* __restrict__ hid,
                            const float* __restrict__ Wq,
                            const float* __restrict__ Wk,
                            const float* __restrict__ Wv) {
    int bid = blockIdx.x;
    if (bid < NA_BLOCKS) {
        long i4 = (long)bid * 256 + threadIdx.x;
        float4 v = reinterpret_cast<const float4*>(hid)[i4];
        __half h[4] = {__float2half_rn(v.x), __float2half_rn(v.y),
                       __float2half_rn(v.z), __float2half_rn(v.w)};
        *reinterpret_cast<ushort4*>(&g_Apack[i4 * 4]) = *reinterpret_cast<ushort4*>(h);
        return;
    }
    __shared__ float tile[32][33];
    int b2 = bid - NA_BLOCKS;
    int k0 = (b2 % NBK) * 32;
    int n0 = (b2 / NBK) * 32;
    const float* W; int ldw, nc;
    if (n0 < NH_ * D_)               { W = Wq; ldw = NH_ * D_;  nc = n0; }
    else if (n0 < (NH_ + NKV_) * D_) { W = Wk; ldw = NKV_ * D_; nc = n0 - NH_ * D_; }
    else                             { W = Wv; ldw = NKV_ * D_; nc = n0 - (NH_ + NKV_) * D_; }
    int tx = threadIdx.x & 31, ty = threadIdx.x >> 5;
#pragma unroll
    for (int r = 0; r < 4; r++)
        tile[ty + r * 8][tx] = W[(long)(k0 + ty + r * 8) * ldw + nc + tx];
    __syncthreads();
#pragma unroll
    for (int r = 0; r < 4; r++) {
        int nl = ty + r * 8;
        g_Bpack[(long)(n0 + nl) * K_ + k0 + tx] = __float2half_rn(tile[tx][nl]);
    }
}

// ---------------- fused GEMM + bias + RoPE (128 thr, 2 CTA/SM, 64x64 tiles, frag pipeline) ----------------
__global__ __launch_bounds__(128, 2)
void qkv_mma_kernel(const float* __restrict__ cosp, const float* __restrict__ sinp,
                    const float* __restrict__ bq, const float* __restrict__ bk,
                    const float* __restrict__ bv, float* __restrict__ out) {
    extern __shared__ char smem[];
    const uint32_t sbase = smem_u32(smem);
    const int tid  = threadIdx.x;
    const int wid  = tid >> 5, lane = tid & 31;
    const int m0   = blockIdx.y * BM;
    const int hg   = blockIdx.x;              // one head per CTA
    const int n0   = hg * BN;

    const int warp_m = wid & 1;               // 2 warps over M (64 rows each)
    const int warp_n = wid >> 1;              // 2 warps over N (64 cols each)

    const __half* Agb = g_Apack + (long)m0 * K_;
    const __half* Bgb = g_Bpack + (long)n0 * K_;

    auto load_stage = [&](int c, int s) {
        const uint32_t ab = sbase + (uint32_t)(s * STAGE_BYTES);
        const uint32_t bb = ab + A_BYTES;
        const __half* Ag = Agb + (long)c * 32;
        const __half* Bg = Bgb + (long)c * 32;
#pragma unroll
        for (int i = 0; i < 4; i++) {
            int e = tid + i * 128, row = e >> 2, q = e & 3;
            cp16(ab + swz64(row * 64 + q * 16), Ag + (long)row * K_ + q * 8);
        }
#pragma unroll
        for (int i = 0; i < 4; i++) {
            int e = tid + i * 128, row = e >> 2, q = e & 3;
            cp16(bb + swz64(row * 64 + q * 16), Bg + (long)row * K_ + q * 8);
        }
    };

    const int a_row = lane & 15;
    const int a_cb  = (lane >> 4) * 16;
    const int b_row = ((lane >> 4) << 3) + (lane & 7);
    const int b_cb  = ((lane >> 3) & 1) * 16;

    // fragment loader: stage slot s, k-step ks -> af/bf
    auto ldm_frags = [&](int s, int ks, uint32_t af[4][4], uint32_t bf[4][4]) {
        const uint32_t ab = sbase + (uint32_t)(s * STAGE_BYTES);
        const uint32_t bb = ab + A_BYTES;
#pragma unroll
        for (int mt = 0; mt < 4; mt++) {
            uint32_t off = (uint32_t)(warp_m * 64 + mt * 16 + a_row) * 64 + ks * 32 + a_cb;
            ldm_x4(af[mt], ab + swz64(off));
        }
#pragma unroll
        for (int bt = 0; bt < 4; bt++) {
            uint32_t off = (uint32_t)(warp_n * 64 + bt * 16 + b_row) * 64 + ks * 32 + b_cb;
            ldm_x4(bf[bt], bb + swz64(off));
        }
    };

    float acc[4][8][4];
#pragma unroll
    for (int i = 0; i < 4; i++)
#pragma unroll
        for (int j = 0; j < 8; j++)
#pragma unroll
            for (int r = 0; r < 4; r++) acc[i][j][r] = 0.f;

    auto do_mma = [&](uint32_t af[4][4], uint32_t bf[4][4]) {
#pragma unroll
        for (int mt = 0; mt < 4; mt++)
#pragma unroll
            for (int nt = 0; nt < 8; nt++)
                mma_f16(acc[mt][nt], af[mt], &bf[nt >> 1][(nt & 1) * 2]);
    };

    uint32_t afA[4][4], bfA[4][4], afB[4][4], bfB[4][4];

    // preamble: stages 0,1,2 in flight; stage 0 visible; frags (0,0) loaded
    load_stage(0, 0); CP_COMMIT();
    load_stage(1, 1); CP_COMMIT();
    load_stage(2, 2); CP_COMMIT();
    CP_WAIT2();                 // stage 0 complete (own groups)
    __syncthreads();            // cross-thread visibility of stage 0
    ldm_frags(0, 0, afA, bfA);

    for (int c = 0; c < NC; c++) {
        // 1. issue next load (slot (c-1)&3; prior iter's barrier ordered last reads)
        if (c + 3 < NC) load_stage(c + 3, (c + 3) & 3);
        CP_COMMIT();            // unconditional: keeps group counting uniform
        // 2. frags (c, ks=1)
        ldm_frags(c & 3, 1, afB, bfB);
        // 3. mma (c, ks=0)
        do_mma(afA, bfA);
        // 4. stage c+1 complete + visible
        CP_WAIT2();
        __syncthreads();
        // 5. frags (c+1, ks=0) — hidden behind mma below
        if (c + 1 < NC) ldm_frags((c + 1) & 3, 0, afA, bfA);
        // 6. mma (c, ks=1)
        do_mma(afB, bfB);
    }

    CP_WAIT0();
    __syncthreads();

    // ---- epilogue: accums -> smem stage ----
    float* stage = reinterpret_cast<float*>(smem);
#pragma unroll
    for (int mt = 0; mt < 4; mt++) {
#pragma unroll
        for (int nt = 0; nt < 8; nt++) {
            int row = warp_m * 64 + mt * 16 + (lane >> 2);
            int col = warp_n * 64 + nt * 8 + (lane & 3) * 2;
            *reinterpret_cast<float2*>(&stage[row * SROW + col]) =
                make_float2(acc[mt][nt][0], acc[mt][nt][1]);
            *reinterpret_cast<float2*>(&stage[(row + 8) * SROW + col]) =
                make_float2(acc[mt][nt][2], acc[mt][nt][3]);
        }
    }
    __syncthreads();

    // ---- bias + RoPE + coalesced store (one head) ----
    bool rope; const float* bias; float* ob; int nheads, hloc;
    if (hg < NH_)             { rope = true;  bias = bq; ob = out;                 nheads = NH_;  hloc = hg; }
    else if (hg < NH_ + NKV_) { rope = true;  bias = bk; ob = out + QSIZE;         nheads = NKV_; hloc = hg - NH_; }
    else                      { rope = false; bias = bv; ob = out + QSIZE + KSIZE; nheads = NKV_; hloc = hg - NH_ - NKV_; }

    const int j0 = lane * 4;                 // own columns
    const int p0 = (j0 + 64) & 127;          // partner columns
    const int d  = j0 & 63;
    float4 bo = *reinterpret_cast<const float4*>(bias + hloc * D_ + j0);
    float4 bp = *reinterpret_cast<const float4*>(bias + hloc * D_ + p0);

    for (int r = 0; r < 32; r++) {
        int row = wid * 32 + r;              // 4 warps x 32 rows = 128
        int m2 = m0 + row;
        int bi = m2 >> 12, sq = m2 & (S_ - 1);
        float4 own = *reinterpret_cast<const float4*>(&stage[row * SROW + j0]);
        float4 par = *reinterpret_cast<const float4*>(&stage[row * SROW + p0]);
        own.x += bo.x; own.y += bo.y; own.z += bo.z; own.w += bo.w;
        par.x += bp.x; par.y += bp.y; par.z += bp.z; par.w += bp.w;
        float4 o;
        if (rope) {
            float4 cc = *reinterpret_cast<const float4*>(cosp + (long)m2 * D_ + d);
            float4 ss = *reinterpret_cast<const float4*>(sinp + (long)m2 * D_ + d);
            if (lane < 16) {   // own = lo half: o = lo*c - hi*s
                o.x = own.x * cc.x - par.x * ss.x;
                o.y = own.y * cc.y - par.y * ss.y;
                o.z = own.z * cc.z - par.z * ss.z;
                o.w = own.w * cc.w - par.w * ss.w;
            } else {           // own = hi half: o = hi*c + lo*s
                o.x = own.x * cc.x + par.x * ss.x;
                o.y = own.y * cc.y + par.y * ss.y;
                o.z = own.z * cc.z + par.z * ss.z;
                o.w = own.w * cc.w + par.w * ss.w;
            }
        } else {
            o = own;
        }
        float* optr = ob + ((long)(bi * nheads + hloc) * S_ + sq) * D_;
        *reinterpret_cast<float4*>(optr + j0) = o;
    }
}

// ---------------- launch ----------------
extern "C" void kernel_launch(void* const* d_in, const int* in_sizes, int n_in,
                              void* d_out, int out_size) {
    (void)in_sizes; (void)n_in; (void)out_size;
    const float* hid  = (const float*)d_in[0];
    const float* cosp = (const float*)d_in[1];
    const float* sinp = (const float*)d_in[2];
    const float* Wq   = (const float*)d_in[3];
    const float* bq   = (const float*)d_in[4];
    const float* Wk   = (const float*)d_in[5];
    const float* bk   = (const float*)d_in[6];
    const float* Wv   = (const float*)d_in[7];
    const float* bv   = (const float*)d_in[8];
    float* out = (float*)d_out;

    cudaFuncSetAttribute(qkv_mma_kernel, cudaFuncAttributeMaxDynamicSharedMemorySize, SMEM_TOTAL);

    conv_kernel<<<NA_BLOCKS + NB_BLOCKS, 256>>>(hid, Wq, Wk, Wv);
    qkv_mma_kernel<<<dim3(NTOT / BN, M_ / BM), 128, SMEM_TOTAL>>>(cosp, sinp, bq, bk, bv, out);
}